// round 9
// baseline (speedup 1.0000x reference)
#include <cuda_runtime.h>
#include <math.h>

#define BB 4096
#define TT 128
#define SS 12288              // 3 * BB channel-chains
#define NSLOT 126             // loss slots u = t-2, t in [2,127]
#define NG 125                // filtered-history slots, t in [2,126], m = t-2
#define NBLK 64

// shared memory layout (floats)
#define SZ_Z   (384 * 66)             // z staged: [k=t*3+ch][64 lanes padded to 66]
#define SZ_SV  (3 * NSLOT * 64)       // Sv table: [ch][u][64]
#define SMEM_FLOATS (SZ_Z + SZ_SV)
#define SMEM_BYTES  (SMEM_FLOATS * 4)

// ---------------- device scratch (no allocations allowed) ----------------
__device__ float4 g_F[NG * SS];    // filtered p,v,Pa,Pb
__device__ float  g_Fc[NG * SS];   // filtered Pc
__device__ float  g_bsum[NBLK];    // per-block partials
__device__ unsigned int g_cnt;     // last-block gate (self-resetting)

static __device__ __forceinline__ float sigmoidf_(float x) {
    return 1.0f / (1.0f + expf(-x));
}
static __device__ __forceinline__ float tanh_fast(float x) {
    float y; asm("tanh.approx.f32 %0, %1;" : "=f"(y) : "f"(x)); return y;
}
static __device__ __forceinline__ float rcp_fast(float x) {
    float y; asm("rcp.approx.f32 %0, %1;" : "=f"(y) : "f"(x)); return y;
}

__global__ void __launch_bounds__(96, 1)
k_all(const float* __restrict__ params,
      const float* __restrict__ covp,
      const float* __restrict__ init_states,
      const float* __restrict__ zin,
      float* __restrict__ out)
{
    extern __shared__ float smem[];
    float* sZ  = smem;                   // [384][66]
    float* sSv = smem + SZ_Z;            // [3][126][64]
    __shared__ bool sLast;

    const int tid  = threadIdx.x;
    const int ch   = tid >> 5;           // warp index = channel
    const int lane = tid & 31;
    const int b0   = (blockIdx.x << 6) + lane;        // chain 0 sequence
    const int b1   = b0 + 32;                         // chain 1 sequence
    const int s0   = ch * BB + b0;
    const int s1   = ch * BB + b1;

    // ---------- stage 64 sequences' measurements into smem (coalesced) ----------
    {
        const float* zblk = zin + (size_t)(blockIdx.x << 6) * (TT * 3);
#pragma unroll 4
        for (int lb = 0; lb < 64; lb++) {
            const float4 vz = reinterpret_cast<const float4*>(zblk + lb * 384)[tid];
            const int k = tid << 2;
            sZ[(k + 0) * 66 + lb] = vz.x;
            sZ[(k + 1) * 66 + lb] = vz.y;
            sZ[(k + 2) * 66 + lb] = vz.z;
            sZ[(k + 3) * 66 + lb] = vz.w;
        }
    }

    const float DT     = 1.0f / 120.0f;
    const float TWO_PI = 6.28318530717958647692f;
    const float INV2PI = 0.15915494309189533577f;
    const float FOLD   = 4.71238898038468985769f;

    const float friction = (tanhf(params[0]) + 1.0f) * 0.01f;
    const float damping  = (tanhf(params[1]) + 1.0f) * 0.01f;

    const float r     = sigmoidf_(covp[ch]);
    const float qp    = sigmoidf_(covp[ch == 2 ? 5 : 3]);
    const float qv    = sigmoidf_(covp[ch == 2 ? 6 : 4]);
    const float gd    = 1.0f - DT * damping;
    const float Df    = DT * friction;
    const float Ag    = DT * friction * 100.0f;
    const float gdmAg = gd - Ag;
    const bool  ang   = (ch == 2);

    // two chains per thread
    float p[2], v[2], Pa[2], Pb[2], Pc[2];
    {
        const int pi = ang ? 4 : ch;
        const int vi = ang ? 5 : (ch + 2);
        p[0] = init_states[b0 * 6 + pi];
        v[0] = init_states[b0 * 6 + vi];
        p[1] = init_states[b1 * 6 + pi];
        v[1] = init_states[b1 * 6 + vi];
    }
#pragma unroll
    for (int k = 0; k < 2; k++) { Pa[k] = 0.01f; Pb[k] = 0.0f; Pc[k] = 0.01f; }

    __syncthreads();   // z staged

#define ZLDS(t, k) sZ[((t) * 3 + ch) * 66 + ((k) << 5) + lane]

    // =========================== FORWARD EKF (store filtered) ===========================
#define FW_BODY(k, zc, tc, scol)                                                 \
    do {                                                                         \
        float g_, spv_;                                                          \
        if (!ang) {                                                              \
            const float th = tanh_fast(100.0f * v[k]);                           \
            spv_ = __fmaf_rn(-Df, th, gd * v[k]);                                \
            g_   = __fmaf_rn(Ag, th * th, gdmAg);                                \
        } else { spv_ = v[k] * gd; g_ = gd; }                                    \
        const float spp_ = __fmaf_rn(DT, v[k], p[k]);                            \
        const float bdc  = __fmaf_rn(DT, Pc[k], Pb[k]);                          \
        const float ap   = __fmaf_rn(DT, Pb[k] + bdc, Pa[k]) + qp;               \
        const float bp   = g_ * bdc;                                             \
        const float cpv  = __fmaf_rn(g_ * g_, Pc[k], qv);                        \
        float innov = (zc) - spp_;                                               \
        if (ang) innov = innov - TWO_PI * rintf(innov * INV2PI);                 \
        const float inv = rcp_fast(ap + r);                                      \
        const float K0  = ap * inv;                                              \
        const float K1  = bp * inv;                                              \
        p[k]  = __fmaf_rn(K0, innov, spp_);                                      \
        v[k]  = __fmaf_rn(K1, innov, spv_);                                      \
        Pa[k] = __fmaf_rn(-K0, ap, ap);                                          \
        Pb[k] = __fmaf_rn(-K0, bp, bp);                                          \
        Pc[k] = __fmaf_rn(-K1, bp, cpv);                                         \
        if ((tc) >= 2 && (tc) <= 126) {                                          \
            const int m_ = (tc) - 2;                                             \
            g_F[m_ * SS + (scol)]  = make_float4(p[k], v[k], Pa[k], Pb[k]);      \
            g_Fc[m_ * SS + (scol)] = Pc[k];                                      \
        }                                                                        \
    } while (0)

    {
        float zc0 = ZLDS(0, 0), zc1 = ZLDS(0, 1);
#pragma unroll 4
        for (int t = 0; t < TT; t++) {
            const float zn0 = (t + 1 < TT) ? ZLDS(t + 1, 0) : 0.0f;
            const float zn1 = (t + 1 < TT) ? ZLDS(t + 1, 1) : 0.0f;
            FW_BODY(0, zc0, t, s0);
            FW_BODY(1, zc1, t, s1);
            zc0 = zn0; zc1 = zn1;
        }
    }
#undef FW_BODY

    float acc = 0.0f;

    // loss at t = 127 (smoothed == filtered), both chains
#pragma unroll
    for (int k = 0; k < 2; k++) {
        const float zf = ZLDS(TT - 1, k);
        float e = zf - p[k];
        if (ang) {
            e = (e >  FOLD) ? e - TWO_PI : e;
            e = (e < -FOLD) ? e + TWO_PI : e;
        }
        const float Sv = Pa[k] + r;
        sSv[(ch * NSLOT + 125) * 64 + (k << 5) + lane] = Sv;
        acc = __fmaf_rn(Sv * e, e, acc);
    }

    // =========================== BACKWARD RTS (recompute G from filtered) ===========================
    float c0[2], c1[2], Q00[2], Q01[2], Q11[2];
#pragma unroll
    for (int k = 0; k < 2; k++) {
        c0[k] = p[k]; c1[k] = v[k];
        Q00[k] = Pa[k]; Q01[k] = Pb[k]; Q11[k] = Pc[k];
    }

    // 4-deep prefetch pipeline per chain
    float4 F[2][4];
    float  C[2][4], Z[2][4];

#define BW_LOAD(k, j, tq, scol)                                                  \
    do { if ((tq) >= 2) {                                                        \
        const int _m = (tq) - 2;                                                 \
        F[k][j] = g_F[_m * SS + (scol)];                                         \
        C[k][j] = g_Fc[_m * SS + (scol)];                                        \
        Z[k][j] = ZLDS(tq, k);                                                   \
    } } while (0)

#define BW_BODY(k, Fv, Cv, Zv, tc)                                               \
    do {                                                                         \
        const float fp = (Fv).x, fv = (Fv).y, fa = (Fv).z, fb = (Fv).w;          \
        const float fc = (Cv);                                                   \
        float g_, spv_;                                                          \
        if (!ang) {                                                              \
            const float th = tanh_fast(100.0f * fv);                             \
            spv_ = __fmaf_rn(-Df, th, gd * fv);                                  \
            g_   = __fmaf_rn(Ag, th * th, gdmAg);                                \
        } else { spv_ = fv * gd; g_ = gd; }                                      \
        const float spp_ = __fmaf_rn(DT, fv, fp);                                \
        const float bdc  = __fmaf_rn(DT, fc, fb);                                \
        const float ap   = __fmaf_rn(DT, fb + bdc, fa) + qp;                     \
        const float bp   = g_ * bdc;                                             \
        const float cpv  = __fmaf_rn(g_ * g_, fc, qv);                           \
        const float idet = rcp_fast(__fmaf_rn(ap, cpv, -bp * bp));               \
        const float u0 = __fmaf_rn(DT, fb, fa);                                  \
        const float u1 = g_ * fb;                                                \
        const float w0 = bdc;                                                    \
        const float w1 = g_ * fc;                                                \
        const float G00 = __fmaf_rn(u0, cpv, -u1 * bp) * idet;                   \
        const float G01 = __fmaf_rn(u1, ap,  -u0 * bp) * idet;                   \
        const float G10 = __fmaf_rn(w0, cpv, -w1 * bp) * idet;                   \
        const float G11 = __fmaf_rn(w1, ap,  -w0 * bp) * idet;                   \
        const float ds0 = c0[k] - spp_;                                          \
        const float ds1 = c1[k] - spv_;                                          \
        const float ssp = __fmaf_rn(G00, ds0, __fmaf_rn(G01, ds1, fp));          \
        const float ssv = __fmaf_rn(G10, ds0, __fmaf_rn(G11, ds1, fv));          \
        const float E00 = Q00[k] - ap;                                           \
        const float E01 = Q01[k] - bp;                                           \
        const float E11 = Q11[k] - cpv;                                          \
        const float M00 = __fmaf_rn(G00, E00, G01 * E01);                        \
        const float M01 = __fmaf_rn(G00, E01, G01 * E11);                        \
        const float M10 = __fmaf_rn(G10, E00, G11 * E01);                        \
        const float M11 = __fmaf_rn(G10, E01, G11 * E11);                        \
        const float nQ00 = __fmaf_rn(M00, G00, __fmaf_rn(M01, G01, fa));         \
        const float nQ01 = __fmaf_rn(M00, G10, __fmaf_rn(M01, G11, fb));         \
        const float nQ11 = __fmaf_rn(M10, G10, __fmaf_rn(M11, G11, fc));         \
        c0[k] = ssp; c1[k] = ssv;                                                \
        Q00[k] = nQ00; Q01[k] = nQ01; Q11[k] = nQ11;                             \
        const float Sv = nQ00 + r;                                               \
        float e = (Zv) - ssp;                                                    \
        if (ang) {                                                               \
            e = (e >  FOLD) ? e - TWO_PI : e;                                    \
            e = (e < -FOLD) ? e + TWO_PI : e;                                    \
        }                                                                        \
        acc = __fmaf_rn(Sv * e, e, acc);                                         \
        sSv[(ch * NSLOT + ((tc) - 2)) * 64 + ((k) << 5) + lane] = Sv;            \
    } while (0)

    // preload slots j=0..3 with t = 126..123
#pragma unroll
    for (int j = 0; j < 4; j++) {
        BW_LOAD(0, j, 126 - j, s0);
        BW_LOAD(1, j, 126 - j, s1);
    }

    // 32 chunks of 4 cover t = 126 down to 2 (125 steps; guards trim the tail)
    for (int ii = 0; ii < 32; ii++) {
        const int head = 126 - 4 * ii;
#pragma unroll
        for (int j = 0; j < 4; j++) {
            const int tc = head - j;
            const float4 Fv0 = F[0][j];
            const float  Cv0 = C[0][j], Zv0 = Z[0][j];
            const float4 Fv1 = F[1][j];
            const float  Cv1 = C[1][j], Zv1 = Z[1][j];
            const int tp = tc - 4;
            BW_LOAD(0, j, tp, s0);
            BW_LOAD(1, j, tp, s1);
            if (tc >= 2) {
                BW_BODY(0, Fv0, Cv0, Zv0, tc);
                BW_BODY(1, Fv1, Cv1, Zv1, tc);
            }
        }
    }
#undef BW_LOAD
#undef BW_BODY
#undef ZLDS

    // =========================== in-block combine ===========================
    __syncthreads();

    float total = acc;
    // 126*64 = 8064 = 84 * 96 exactly
    for (int idx = tid; idx < NSLOT * 64; idx += 96) {
        const int u = idx >> 6;
        const int l = idx & 63;
        total += sSv[(0 * NSLOT + u) * 64 + l]
               * sSv[(1 * NSLOT + u) * 64 + l]
               * sSv[(2 * NSLOT + u) * 64 + l];
    }
    __syncthreads();            // all Sv reads done; reuse smem front as scratch
    sSv[tid] = total;
    if (tid < 32) sSv[96 + tid] = 0.0f;
    __syncthreads();
#pragma unroll
    for (int k = 64; k > 0; k >>= 1) {
        if (tid < k) sSv[tid] += sSv[tid + k];
        __syncthreads();
    }
    if (tid == 0) g_bsum[blockIdx.x] = sSv[0];
    __threadfence();
    if (tid == 0) {
        const unsigned int old = atomicInc(&g_cnt, NBLK - 1u);
        sLast = (old == NBLK - 1u);
    }
    __syncthreads();

    // last block: deterministic final reduce of 64 partials
    if (sLast && tid < 32) {
        __threadfence();
        double ds = (double)g_bsum[2 * tid] + (double)g_bsum[2 * tid + 1];
#pragma unroll
        for (int k = 16; k > 0; k >>= 1)
            ds += __shfl_xor_sync(0xffffffffu, ds, k);
        if (tid == 0) out[0] = (float)ds;
    }
}

// ---------------- launch ----------------
extern "C" void kernel_launch(void* const* d_in, const int* in_sizes, int n_in,
                              void* d_out, int out_size) {
    const float* params = nullptr;
    const float* covp   = nullptr;
    const float* init   = nullptr;
    const float* meas   = nullptr;

    for (int i = 0; i < n_in; i++) {
        if      (in_sizes[i] == 4)            params = (const float*)d_in[i];
        else if (in_sizes[i] == 7)            covp   = (const float*)d_in[i];
        else if (in_sizes[i] == BB * 6)       init   = (const float*)d_in[i];
        else if (in_sizes[i] == BB * TT * 3)  meas   = (const float*)d_in[i];
    }
    if (!params && n_in > 0) params = (const float*)d_in[0];
    if (!covp   && n_in > 1) covp   = (const float*)d_in[1];
    if (!init   && n_in > 2) init   = (const float*)d_in[2];
    if (!meas   && n_in > 3) meas   = (const float*)d_in[3];

    static int smem_set = 0;
    if (!smem_set) {
        cudaFuncSetAttribute(k_all, cudaFuncAttributeMaxDynamicSharedMemorySize,
                             SMEM_BYTES);
        smem_set = 1;
    }

    k_all<<<NBLK, 96, SMEM_BYTES>>>(params, covp, init, meas, (float*)d_out);
}

// round 10
// speedup vs baseline: 1.1143x; 1.1143x over previous
#include <cuda_runtime.h>
#include <math.h>

#define BB 4096
#define TT 128
#define SS 12288              // 3 * BB chains
#define NHS 90                // history slots in smem (m = t-2 in [0,90))
#define NGG 35                // history slots in global (m in [90,125))
#define NBLK 128

// shared memory layout (floats)
#define SZ_Z (384 * 33)       // z staged: [k=t*3+ch][lane]
#define SZ_H (NHS * 480)      // history: [m][c*128 + lane*4 (float4)] + [m][384 + c*32 + lane]
#define SMEM_BYTES ((SZ_Z + SZ_H) * 4)

// ---------------- device scratch (no allocations allowed) ----------------
__device__ float4 g_F4[NGG * SS];   // filtered p,v,Pa,Pb (high-t slots)
__device__ float  g_Fc[NGG * SS];   // filtered Pc
__device__ float  g_bsum[NBLK];     // per-block partials
__device__ unsigned int g_cnt;      // last-block gate (self-resetting)

static __device__ __forceinline__ float sigmoidf_(float x) {
    return 1.0f / (1.0f + expf(-x));
}
static __device__ __forceinline__ float tanh_fast(float x) {
    float y; asm("tanh.approx.f32 %0, %1;" : "=f"(y) : "f"(x)); return y;
}
static __device__ __forceinline__ float rcp_fast(float x) {
    float y; asm("rcp.approx.f32 %0, %1;" : "=f"(y) : "f"(x)); return y;
}

__global__ void __launch_bounds__(32, 1)
k_all(const float* __restrict__ params,
      const float* __restrict__ covp,
      const float* __restrict__ init_states,
      const float* __restrict__ zin,
      float* __restrict__ out)
{
    extern __shared__ float smem[];
    float* sZ = smem;                 // [384][33]
    float* sH = smem + SZ_Z;          // [NHS][480]

    const int lane = threadIdx.x;
    const int b    = (blockIdx.x << 5) + lane;

    // ---------- stage this block's 32 sequences into smem (coalesced) ----------
    {
        const float* zblk = zin + (size_t)(blockIdx.x << 5) * 384;
        for (int lb = 0; lb < 32; lb++) {
            const float4* rp = reinterpret_cast<const float4*>(zblk + (size_t)lb * 384);
#pragma unroll
            for (int j = 0; j < 3; j++) {
                const float4 vz = rp[j * 32 + lane];
                const int k = (j * 32 + lane) << 2;
                sZ[(k + 0) * 33 + lb] = vz.x;
                sZ[(k + 1) * 33 + lb] = vz.y;
                sZ[(k + 2) * 33 + lb] = vz.z;
                sZ[(k + 3) * 33 + lb] = vz.w;
            }
        }
    }

    const float DT     = 1.0f / 120.0f;
    const float TWO_PI = 6.28318530717958647692f;
    const float INV2PI = 0.15915494309189533577f;
    const float FOLD   = 4.71238898038468985769f;

    const float friction = (tanhf(params[0]) + 1.0f) * 0.01f;
    const float damping  = (tanhf(params[1]) + 1.0f) * 0.01f;

    float r_[3], qp_[3], qv_[3];
#pragma unroll
    for (int c = 0; c < 3; c++) {
        r_[c]  = sigmoidf_(covp[c]);
        qp_[c] = sigmoidf_(covp[c == 2 ? 5 : 3]);
        qv_[c] = sigmoidf_(covp[c == 2 ? 6 : 4]);
    }
    const float gd    = 1.0f - DT * damping;
    const float Df    = DT * friction;
    const float Ag    = DT * friction * 100.0f;
    const float gdmAg = gd - Ag;

    // 3 channel-chains per thread
    float p[3], v[3], Pa[3], Pb[3], Pc[3];
    p[0] = init_states[b * 6 + 0];
    p[1] = init_states[b * 6 + 1];
    p[2] = init_states[b * 6 + 4];
    v[0] = init_states[b * 6 + 2];
    v[1] = init_states[b * 6 + 3];
    v[2] = init_states[b * 6 + 5];
#pragma unroll
    for (int c = 0; c < 3; c++) { Pa[c] = 0.01f; Pb[c] = 0.0f; Pc[c] = 0.01f; }

    __syncthreads();   // z staged

#define ZLDS(t, c) sZ[((t) * 3 + (c)) * 33 + lane]

    // =========================== FORWARD EKF ===========================
    {
        float zc[3], zn[3];
#pragma unroll
        for (int c = 0; c < 3; c++) zc[c] = ZLDS(0, c);

#pragma unroll 4
        for (int t = 0; t < TT; t++) {
#pragma unroll
            for (int c = 0; c < 3; c++) zn[c] = (t + 1 < TT) ? ZLDS(t + 1, c) : 0.0f;

#pragma unroll
            for (int c = 0; c < 3; c++) {
                const bool ang = (c == 2);
                float g_, spv_;
                if (!ang) {
                    const float th = tanh_fast(100.0f * v[c]);
                    spv_ = __fmaf_rn(-Df, th, gd * v[c]);
                    g_   = __fmaf_rn(Ag, th * th, gdmAg);
                } else { spv_ = v[c] * gd; g_ = gd; }
                const float spp_ = __fmaf_rn(DT, v[c], p[c]);
                const float bdc  = __fmaf_rn(DT, Pc[c], Pb[c]);
                const float ap   = __fmaf_rn(DT, Pb[c] + bdc, Pa[c]) + qp_[c];
                const float bp   = g_ * bdc;
                const float cpv  = __fmaf_rn(g_ * g_, Pc[c], qv_[c]);
                float innov = zc[c] - spp_;
                if (ang) innov = innov - TWO_PI * rintf(innov * INV2PI);
                const float inv = rcp_fast(ap + r_[c]);
                const float K0  = ap * inv;
                const float K1  = bp * inv;
                p[c]  = __fmaf_rn(K0, innov, spp_);
                v[c]  = __fmaf_rn(K1, innov, spv_);
                Pa[c] = __fmaf_rn(-K0, ap, ap);
                Pb[c] = __fmaf_rn(-K0, bp, bp);
                Pc[c] = __fmaf_rn(-K1, bp, cpv);
            }

            if (t >= 2 && t <= 126) {
                const int m = t - 2;
                if (m < NHS) {
                    float* hp = sH + m * 480;
#pragma unroll
                    for (int c = 0; c < 3; c++) {
                        reinterpret_cast<float4*>(hp + c * 128)[lane] =
                            make_float4(p[c], v[c], Pa[c], Pb[c]);
                        hp[384 + c * 32 + lane] = Pc[c];
                    }
                } else {
                    const int gi = (m - NHS) * SS + b;
#pragma unroll
                    for (int c = 0; c < 3; c++) {
                        g_F4[gi + c * BB] = make_float4(p[c], v[c], Pa[c], Pb[c]);
                        g_Fc[gi + c * BB] = Pc[c];
                    }
                }
            }
#pragma unroll
            for (int c = 0; c < 3; c++) zc[c] = zn[c];
        }
    }

    // loss at t = 127 (smoothed == filtered) — fully local
    float acc;
    {
        float Sv[3], e[3];
#pragma unroll
        for (int c = 0; c < 3; c++) {
            Sv[c] = Pa[c] + r_[c];
            e[c]  = ZLDS(TT - 1, c) - p[c];
        }
        e[2] = (e[2] >  FOLD) ? e[2] - TWO_PI : e[2];
        e[2] = (e[2] < -FOLD) ? e[2] + TWO_PI : e[2];
        acc = Sv[0] * Sv[1] * Sv[2]
            + Sv[0] * e[0] * e[0] + Sv[1] * e[1] * e[1] + Sv[2] * e[2] * e[2];
    }

    // =========================== BACKWARD RTS (recompute G) ===========================
    float c0[3], c1[3], Q00[3], Q01[3], Q11[3];
#pragma unroll
    for (int c = 0; c < 3; c++) {
        c0[c] = p[c]; c1[c] = v[c];
        Q00[c] = Pa[c]; Q01[c] = Pb[c]; Q11[c] = Pc[c];
    }

    float4 FA[3], FB[3];
    float  CA[3], CB[3], ZA[3], ZB[3];

#define BW_PREF(F_, C_, Z_, tq)                                                  \
    do { if ((tq) >= 2) {                                                        \
        const int _m = (tq) - 2;                                                 \
        if (_m < NHS) {                                                          \
            const float* hp = sH + _m * 480;                                     \
            _Pragma("unroll")                                                    \
            for (int c = 0; c < 3; c++) {                                        \
                F_[c] = reinterpret_cast<const float4*>(hp + c * 128)[lane];     \
                C_[c] = hp[384 + c * 32 + lane];                                 \
            }                                                                    \
        } else {                                                                 \
            const int gi = (_m - NHS) * SS + b;                                  \
            _Pragma("unroll")                                                    \
            for (int c = 0; c < 3; c++) {                                        \
                F_[c] = g_F4[gi + c * BB];                                       \
                C_[c] = g_Fc[gi + c * BB];                                       \
            }                                                                    \
        }                                                                        \
        _Pragma("unroll")                                                        \
        for (int c = 0; c < 3; c++) Z_[c] = ZLDS(tq, c);                         \
    } } while (0)

#define BW_STEP(F_, C_, Z_, tc)                                                  \
    do {                                                                         \
        float Sv[3], e[3];                                                       \
        _Pragma("unroll")                                                        \
        for (int c = 0; c < 3; c++) {                                            \
            const bool ang = (c == 2);                                           \
            const float fp = F_[c].x, fv = F_[c].y, fa = F_[c].z, fb = F_[c].w;  \
            const float fc = C_[c];                                              \
            float g_, spv_;                                                      \
            if (!ang) {                                                          \
                const float th = tanh_fast(100.0f * fv);                         \
                spv_ = __fmaf_rn(-Df, th, gd * fv);                              \
                g_   = __fmaf_rn(Ag, th * th, gdmAg);                            \
            } else { spv_ = fv * gd; g_ = gd; }                                  \
            const float spp_ = __fmaf_rn(DT, fv, fp);                            \
            const float bdc  = __fmaf_rn(DT, fc, fb);                            \
            const float ap   = __fmaf_rn(DT, fb + bdc, fa) + qp_[c];             \
            const float bp   = g_ * bdc;                                         \
            const float cpv  = __fmaf_rn(g_ * g_, fc, qv_[c]);                   \
            const float idet = rcp_fast(__fmaf_rn(ap, cpv, -bp * bp));           \
            const float u0 = __fmaf_rn(DT, fb, fa);                              \
            const float u1 = g_ * fb;                                            \
            const float w0 = bdc;                                                \
            const float w1 = g_ * fc;                                            \
            const float G00 = __fmaf_rn(u0, cpv, -u1 * bp) * idet;               \
            const float G01 = __fmaf_rn(u1, ap,  -u0 * bp) * idet;               \
            const float G10 = __fmaf_rn(w0, cpv, -w1 * bp) * idet;               \
            const float G11 = __fmaf_rn(w1, ap,  -w0 * bp) * idet;               \
            const float ds0 = c0[c] - spp_;                                      \
            const float ds1 = c1[c] - spv_;                                      \
            const float ssp = __fmaf_rn(G00, ds0, __fmaf_rn(G01, ds1, fp));      \
            const float ssv = __fmaf_rn(G10, ds0, __fmaf_rn(G11, ds1, fv));      \
            const float E00 = Q00[c] - ap;                                       \
            const float E01 = Q01[c] - bp;                                       \
            const float E11 = Q11[c] - cpv;                                      \
            const float M00 = __fmaf_rn(G00, E00, G01 * E01);                    \
            const float M01 = __fmaf_rn(G00, E01, G01 * E11);                    \
            const float M10 = __fmaf_rn(G10, E00, G11 * E01);                    \
            const float M11 = __fmaf_rn(G10, E01, G11 * E11);                    \
            const float nQ00 = __fmaf_rn(M00, G00, __fmaf_rn(M01, G01, fa));     \
            const float nQ01 = __fmaf_rn(M00, G10, __fmaf_rn(M01, G11, fb));     \
            const float nQ11 = __fmaf_rn(M10, G10, __fmaf_rn(M11, G11, fc));     \
            c0[c] = ssp; c1[c] = ssv;                                            \
            Q00[c] = nQ00; Q01[c] = nQ01; Q11[c] = nQ11;                         \
            Sv[c] = nQ00 + r_[c];                                                \
            e[c]  = Z_[c] - ssp;                                                 \
        }                                                                        \
        e[2] = (e[2] >  FOLD) ? e[2] - TWO_PI : e[2];                            \
        e[2] = (e[2] < -FOLD) ? e[2] + TWO_PI : e[2];                            \
        acc += Sv[0] * Sv[1] * Sv[2]                                             \
             + Sv[0] * e[0] * e[0] + Sv[1] * e[1] * e[1] + Sv[2] * e[2] * e[2];  \
    } while (0)

    BW_PREF(FA, CA, ZA, 126);
    BW_PREF(FB, CB, ZB, 125);

    int t = 126;
    for (;;) {
        {
            const float4 F0 = FA[0], F1 = FA[1], F2 = FA[2];
            const float  C0 = CA[0], C1 = CA[1], C2 = CA[2];
            const float  Z0 = ZA[0], Z1 = ZA[1], Z2 = ZA[2];
            float4 Ft[3] = {F0, F1, F2};
            float  Ct[3] = {C0, C1, C2};
            float  Zt[3] = {Z0, Z1, Z2};
            BW_PREF(FA, CA, ZA, t - 2);
            BW_STEP(Ft, Ct, Zt, t);
            if (--t < 2) break;
        }
        {
            const float4 F0 = FB[0], F1 = FB[1], F2 = FB[2];
            const float  C0 = CB[0], C1 = CB[1], C2 = CB[2];
            const float  Z0 = ZB[0], Z1 = ZB[1], Z2 = ZB[2];
            float4 Ft[3] = {F0, F1, F2};
            float  Ct[3] = {C0, C1, C2};
            float  Zt[3] = {Z0, Z1, Z2};
            BW_PREF(FB, CB, ZB, t - 2);
            BW_STEP(Ft, Ct, Zt, t);
            if (--t < 2) break;
        }
    }
#undef BW_PREF
#undef BW_STEP
#undef ZLDS

    // =========================== reduction ===========================
    // warp-level deterministic reduce
#pragma unroll
    for (int k = 16; k > 0; k >>= 1)
        acc += __shfl_xor_sync(0xffffffffu, acc, k);

    if (lane == 0) g_bsum[blockIdx.x] = acc;
    __threadfence();

    unsigned int old = 0;
    if (lane == 0) old = atomicInc(&g_cnt, NBLK - 1u);
    const bool last = __shfl_sync(0xffffffffu, (lane == 0) ? (old == NBLK - 1u) : 0, 0);

    if (last) {
        __threadfence();
        double ds = 0.0;
#pragma unroll
        for (int j = 0; j < 4; j++) ds += (double)g_bsum[lane * 4 + j];
#pragma unroll
        for (int k = 16; k > 0; k >>= 1)
            ds += __shfl_xor_sync(0xffffffffu, ds, k);
        if (lane == 0) out[0] = (float)ds;
    }
}

// ---------------- launch ----------------
extern "C" void kernel_launch(void* const* d_in, const int* in_sizes, int n_in,
                              void* d_out, int out_size) {
    const float* params = nullptr;
    const float* covp   = nullptr;
    const float* init   = nullptr;
    const float* meas   = nullptr;

    for (int i = 0; i < n_in; i++) {
        if      (in_sizes[i] == 4)            params = (const float*)d_in[i];
        else if (in_sizes[i] == 7)            covp   = (const float*)d_in[i];
        else if (in_sizes[i] == BB * 6)       init   = (const float*)d_in[i];
        else if (in_sizes[i] == BB * TT * 3)  meas   = (const float*)d_in[i];
    }
    if (!params && n_in > 0) params = (const float*)d_in[0];
    if (!covp   && n_in > 1) covp   = (const float*)d_in[1];
    if (!init   && n_in > 2) init   = (const float*)d_in[2];
    if (!meas   && n_in > 3) meas   = (const float*)d_in[3];

    static int smem_set = 0;
    if (!smem_set) {
        cudaFuncSetAttribute(k_all, cudaFuncAttributeMaxDynamicSharedMemorySize,
                             SMEM_BYTES);
        smem_set = 1;
    }

    k_all<<<NBLK, 32, SMEM_BYTES>>>(params, covp, init, meas, (float*)d_out);
}

// round 11
// speedup vs baseline: 1.5906x; 1.4275x over previous
#include <cuda_runtime.h>
#include <math.h>

#define BB 4096
#define TT 128
#define SS 12288              // 3 * BB channel-chains
#define NSLOT 126             // loss slots u = t-2, t in [2,127]
#define NG 125                // filtered-history slots, t in [2,126], m = t-2
#define NH4 52                // history slots whose float4 lives in smem

// shared memory layout (floats)
#define SZ_Z   (384 * 33)             // z staged: [k=t*3+ch][lane] padded
#define SZ_SV  (3 * NSLOT * 32)       // Sv table: [ch][u][lane]
#define SZ_D   (NG * 96)              // Pc history: [m][tid]
#define SZ_H4  (NH4 * 384)            // float4 history: [m][tid] (as 4 floats)
#define SMEM_FLOATS (SZ_Z + SZ_SV + SZ_D + SZ_H4)
#define SMEM_BYTES  (SMEM_FLOATS * 4)

// ---------------- device scratch (no allocations allowed) ----------------
__device__ float4 g_F[NG * SS];    // filtered p,v,Pa,Pb (used for m >= NH4)
__device__ float  g_bsum[128];     // per-block partials
__device__ unsigned int g_cnt;     // last-block gate (self-resetting)

static __device__ __forceinline__ float sigmoidf_(float x) {
    return 1.0f / (1.0f + expf(-x));
}
static __device__ __forceinline__ float tanh_fast(float x) {
    float y; asm("tanh.approx.f32 %0, %1;" : "=f"(y) : "f"(x)); return y;
}
static __device__ __forceinline__ float rcp_fast(float x) {
    float y; asm("rcp.approx.f32 %0, %1;" : "=f"(y) : "f"(x)); return y;
}

__global__ void __launch_bounds__(96, 1)
k_all(const float* __restrict__ params,
      const float* __restrict__ covp,
      const float* __restrict__ init_states,
      const float* __restrict__ zin,
      float* __restrict__ out)
{
    extern __shared__ float smem[];
    float* sZ  = smem;                            // [384][33]
    float* sSv = smem + SZ_Z;                     // [3][126][32]
    float* sD  = smem + SZ_Z + SZ_SV;             // [125][96]
    float* sH4 = smem + SZ_Z + SZ_SV + SZ_D;      // [52][96] float4
    __shared__ bool sLast;

    const int tid  = threadIdx.x;
    const int ch   = tid >> 5;           // warp index = channel
    const int lane = tid & 31;
    const int b    = (blockIdx.x << 5) + lane;
    const int s    = ch * BB + b;        // column in g_F

    // ---------- stage this block's measurements into smem (coalesced) ----------
    {
        const float* zblk = zin + (size_t)(blockIdx.x << 5) * (TT * 3);
#pragma unroll 4
        for (int lb = 0; lb < 32; lb++) {
            const float4 vz = reinterpret_cast<const float4*>(zblk + lb * 384)[tid];
            const int k = tid << 2;
            sZ[(k + 0) * 33 + lb] = vz.x;
            sZ[(k + 1) * 33 + lb] = vz.y;
            sZ[(k + 2) * 33 + lb] = vz.z;
            sZ[(k + 3) * 33 + lb] = vz.w;
        }
    }

    const float DT     = 1.0f / 120.0f;
    const float TWO_PI = 6.28318530717958647692f;
    const float INV2PI = 0.15915494309189533577f;
    const float FOLD   = 4.71238898038468985769f;

    const float friction = (tanhf(params[0]) + 1.0f) * 0.01f;
    const float damping  = (tanhf(params[1]) + 1.0f) * 0.01f;

    const float r     = sigmoidf_(covp[ch]);
    const float qp    = sigmoidf_(covp[ch == 2 ? 5 : 3]);
    const float qv    = sigmoidf_(covp[ch == 2 ? 6 : 4]);
    const float gd    = 1.0f - DT * damping;
    const float Df    = DT * friction;
    const float Ag    = DT * friction * 100.0f;
    const float gdmAg = gd - Ag;
    const bool  ang   = (ch == 2);

    float p, v, Pa = 0.01f, Pb = 0.0f, Pc = 0.01f;
    {
        const int pi = ang ? 4 : ch;
        const int vi = ang ? 5 : (ch + 2);
        p = init_states[b * 6 + pi];
        v = init_states[b * 6 + vi];
    }

    __syncthreads();   // z staged

#define ZLDS(t) sZ[((t) * 3 + ch) * 33 + lane]

    // =========================== FORWARD EKF (store filtered only) ===========================
#define FW_STEP(tc, zc)                                                          \
    do {                                                                         \
        float g_, spv_;                                                          \
        if (!ang) {                                                              \
            const float th = tanh_fast(100.0f * v);                              \
            spv_ = __fmaf_rn(-Df, th, gd * v);                                   \
            g_   = __fmaf_rn(Ag, th * th, gdmAg);                                \
        } else { spv_ = v * gd; g_ = gd; }                                       \
        const float spp_ = __fmaf_rn(DT, v, p);                                  \
        const float bdc  = __fmaf_rn(DT, Pc, Pb);                                \
        const float ap   = __fmaf_rn(DT, Pb + bdc, Pa) + qp;                     \
        const float bp   = g_ * bdc;                                             \
        const float cpv  = __fmaf_rn(g_ * g_, Pc, qv);                           \
        float innov = (zc) - spp_;                                               \
        if (ang) innov = innov - TWO_PI * rintf(innov * INV2PI);                 \
        const float inv = rcp_fast(ap + r);                                      \
        const float K0  = ap * inv;                                              \
        const float K1  = bp * inv;                                              \
        p  = __fmaf_rn(K0, innov, spp_);                                         \
        v  = __fmaf_rn(K1, innov, spv_);                                         \
        Pa = r * K0;                                                             \
        Pb = r * K1;                                                             \
        Pc = __fmaf_rn(-K1, bp, cpv);                                            \
        if ((tc) >= 2 && (tc) <= 126) {                                          \
            const int m_ = (tc) - 2;                                             \
            const float4 fq = make_float4(p, v, Pa, Pb);                         \
            if (m_ < NH4) reinterpret_cast<float4*>(sH4 + m_ * 384)[tid] = fq;   \
            else          g_F[m_ * SS + s] = fq;                                 \
            sD[m_ * 96 + tid] = Pc;                                              \
        }                                                                        \
    } while (0)

    {
        float zcur = ZLDS(0);
#pragma unroll 4
        for (int t = 0; t < TT; t++) {
            const float znext = (t + 1 < TT) ? ZLDS(t + 1) : 0.0f;
            FW_STEP(t, zcur);
            zcur = znext;
        }
    }
#undef FW_STEP

    // loss at t = 127 (smoothed == filtered)
    float acc;
    {
        const float zf = ZLDS(TT - 1);
        float e = zf - p;
        if (ang) {
            e = (e >  FOLD) ? e - TWO_PI : e;
            e = (e < -FOLD) ? e + TWO_PI : e;
        }
        const float Sv = Pa + r;
        sSv[(ch * NSLOT + 125) * 32 + lane] = Sv;
        acc = Sv * e * e;
    }

    // =========================== BACKWARD RTS (recompute G from filtered) ===========================
    float c0 = p, c1 = v, Q00 = Pa, Q01 = Pb, Q11 = Pc;

    float4 Fa[4], Fb[4];
    float  Ca[4], Cb[4], Za[4], Zb[4];
#pragma unroll
    for (int j = 0; j < 4; j++) {
        Fa[j] = make_float4(0,0,0,0); Fb[j] = Fa[j];
        Ca[j] = Cb[j] = Za[j] = Zb[j] = 0.0f;
    }

#define BW_LOAD(F_, C_, Z_, tq)                                                  \
    do { if ((tq) >= 2) {                                                        \
        const int _m = (tq) - 2;                                                 \
        if (_m < NH4) F_ = reinterpret_cast<const float4*>(sH4 + _m * 384)[tid]; \
        else          F_ = g_F[_m * SS + s];                                     \
        C_ = sD[_m * 96 + tid];                                                  \
        Z_ = ZLDS(tq);                                                           \
    } } while (0)

#define BW_STEP(Fv, Cv, Zv, tc)                                                  \
    do { if ((tc) >= 2) {                                                        \
        const float fp = (Fv).x, fv = (Fv).y, fa = (Fv).z, fb = (Fv).w;          \
        const float fc = (Cv);                                                   \
        float g_, spv_;                                                          \
        if (!ang) {                                                              \
            const float th = tanh_fast(100.0f * fv);                             \
            spv_ = __fmaf_rn(-Df, th, gd * fv);                                  \
            g_   = __fmaf_rn(Ag, th * th, gdmAg);                                \
        } else { spv_ = fv * gd; g_ = gd; }                                      \
        const float spp_ = __fmaf_rn(DT, fv, fp);                                \
        const float bdc  = __fmaf_rn(DT, fc, fb);                                \
        const float ap   = __fmaf_rn(DT, fb + bdc, fa) + qp;                     \
        const float bp   = g_ * bdc;                                             \
        const float cpv  = __fmaf_rn(g_ * g_, fc, qv);                           \
        const float idet = rcp_fast(__fmaf_rn(ap, cpv, -bp * bp));               \
        const float cpvI = cpv * idet;                                           \
        const float bpI  = bp  * idet;                                           \
        const float apI  = ap  * idet;                                           \
        const float u0 = __fmaf_rn(DT, fb, fa);                                  \
        const float u1 = g_ * fb;                                                \
        const float w0 = bdc;                                                    \
        const float w1 = g_ * fc;                                                \
        const float G00 = __fmaf_rn(u0, cpvI, -u1 * bpI);                        \
        const float G01 = __fmaf_rn(u1, apI,  -u0 * bpI);                        \
        const float G10 = __fmaf_rn(w0, cpvI, -w1 * bpI);                        \
        const float G11 = __fmaf_rn(w1, apI,  -w0 * bpI);                        \
        const float ds0 = c0 - spp_;                                             \
        const float ds1 = c1 - spv_;                                             \
        const float ssp = __fmaf_rn(G00, ds0, __fmaf_rn(G01, ds1, fp));          \
        const float ssv = __fmaf_rn(G10, ds0, __fmaf_rn(G11, ds1, fv));          \
        const float E00 = Q00 - ap;                                              \
        const float E01 = Q01 - bp;                                              \
        const float E11 = Q11 - cpv;                                             \
        const float M00 = __fmaf_rn(G00, E00, G01 * E01);                        \
        const float M01 = __fmaf_rn(G00, E01, G01 * E11);                        \
        const float M10 = __fmaf_rn(G10, E00, G11 * E01);                        \
        const float M11 = __fmaf_rn(G10, E01, G11 * E11);                        \
        const float nQ00 = __fmaf_rn(M00, G00, __fmaf_rn(M01, G01, fa));         \
        const float nQ01 = __fmaf_rn(M00, G10, __fmaf_rn(M01, G11, fb));         \
        const float nQ11 = __fmaf_rn(M10, G10, __fmaf_rn(M11, G11, fc));         \
        c0 = ssp; c1 = ssv; Q00 = nQ00; Q01 = nQ01; Q11 = nQ11;                  \
        const float Sv = nQ00 + r;                                               \
        float e = (Zv) - ssp;                                                    \
        if (ang) {                                                               \
            e = (e >  FOLD) ? e - TWO_PI : e;                                    \
            e = (e < -FOLD) ? e + TWO_PI : e;                                    \
        }                                                                        \
        acc = __fmaf_rn(Sv * e, e, acc);                                         \
        sSv[(ch * NSLOT + ((tc) - 2)) * 32 + lane] = Sv;                         \
    } } while (0)

#pragma unroll
    for (int j = 0; j < 4; j++) BW_LOAD(Fa[j], Ca[j], Za[j], 126 - j);
#pragma unroll
    for (int j = 0; j < 4; j++) BW_LOAD(Fb[j], Cb[j], Zb[j], 122 - j);

    for (int ii = 0; ii < 16; ii++) {
        const int head_a = 126 - 8 * ii;
        const int pre_a  = head_a - 8;
#pragma unroll
        for (int j = 0; j < 4; j++) {
            const float4 Fv = Fa[j];
            const float  Cv = Ca[j], Zv = Za[j];
            BW_LOAD(Fa[j], Ca[j], Za[j], pre_a - j);
            BW_STEP(Fv, Cv, Zv, head_a - j);
        }
        const int head_b = head_a - 4;
        const int pre_b  = head_b - 8;
#pragma unroll
        for (int j = 0; j < 4; j++) {
            const float4 Fv = Fb[j];
            const float  Cv = Cb[j], Zv = Zb[j];
            BW_LOAD(Fb[j], Cb[j], Zb[j], pre_b - j);
            BW_STEP(Fv, Cv, Zv, head_b - j);
        }
    }
#undef BW_LOAD
#undef BW_STEP
#undef ZLDS

    // =========================== in-block combine ===========================
    __syncthreads();

    float total = acc;
    // 126*32 = 4032 = 42 * 96 exactly
    for (int idx = tid; idx < NSLOT * 32; idx += 96) {
        const int u = idx >> 5;
        const int l = idx & 31;
        total += sSv[(0 * NSLOT + u) * 32 + l]
               * sSv[(1 * NSLOT + u) * 32 + l]
               * sSv[(2 * NSLOT + u) * 32 + l];
    }
    // warp-level reduce, then 3 partials via smem
#pragma unroll
    for (int k = 16; k > 0; k >>= 1)
        total += __shfl_xor_sync(0xffffffffu, total, k);
    __syncthreads();            // all Sv reads done; reuse smem front as scratch
    if (lane == 0) sSv[ch] = total;
    __syncthreads();
    if (tid == 0) g_bsum[blockIdx.x] = sSv[0] + sSv[1] + sSv[2];
    __threadfence();
    if (tid == 0) {
        const unsigned int old = atomicInc(&g_cnt, 127u);
        sLast = (old == 127u);
    }
    __syncthreads();

    // last block: deterministic final reduce of 128 partials
    if (sLast && tid < 32) {
        __threadfence();
        double ds = 0.0;
#pragma unroll
        for (int j = 0; j < 4; j++) ds += (double)g_bsum[tid * 4 + j];
#pragma unroll
        for (int k = 16; k > 0; k >>= 1)
            ds += __shfl_xor_sync(0xffffffffu, ds, k);
        if (tid == 0) out[0] = (float)ds;
    }
}

// ---------------- launch ----------------
extern "C" void kernel_launch(void* const* d_in, const int* in_sizes, int n_in,
                              void* d_out, int out_size) {
    const float* params = nullptr;
    const float* covp   = nullptr;
    const float* init   = nullptr;
    const float* meas   = nullptr;

    for (int i = 0; i < n_in; i++) {
        if      (in_sizes[i] == 4)            params = (const float*)d_in[i];
        else if (in_sizes[i] == 7)            covp   = (const float*)d_in[i];
        else if (in_sizes[i] == BB * 6)       init   = (const float*)d_in[i];
        else if (in_sizes[i] == BB * TT * 3)  meas   = (const float*)d_in[i];
    }
    if (!params && n_in > 0) params = (const float*)d_in[0];
    if (!covp   && n_in > 1) covp   = (const float*)d_in[1];
    if (!init   && n_in > 2) init   = (const float*)d_in[2];
    if (!meas   && n_in > 3) meas   = (const float*)d_in[3];

    static int smem_set = 0;
    if (!smem_set) {
        cudaFuncSetAttribute(k_all, cudaFuncAttributeMaxDynamicSharedMemorySize,
                             SMEM_BYTES);
        smem_set = 1;
    }

    k_all<<<128, 96, SMEM_BYTES>>>(params, covp, init, meas, (float*)d_out);
}

// round 12
// speedup vs baseline: 1.9681x; 1.2373x over previous
#include <cuda_runtime.h>
#include <math.h>

#define BB 4096
#define TT 128
#define SS 12288              // 3 * BB channel-chains
#define NSLOT 126             // loss slots u = t-2, t in [2,127]
#define NG 125                // filtered-history slots, t in [2,126], m = t-2

// shared memory layout (floats)
#define SZ_Z   (384 * 33)             // z staged: [k=t*3+ch][lane] padded
#define SZ_SV  (3 * NSLOT * 32)       // Sv table: [ch][u][lane]
#define SZ_D   (NG * 96)              // Pc history: [m][tid]
#define SMEM_FLOATS (SZ_Z + SZ_SV + SZ_D)
#define SMEM_BYTES  (SMEM_FLOATS * 4)

// ---------------- device scratch (no allocations allowed) ----------------
__device__ float4 g_F[NG * SS];    // filtered p,v,Pa,Pb
__device__ float  g_bsum[128];     // per-block partials
__device__ unsigned int g_cnt;     // last-block gate (self-resetting)

static __device__ __forceinline__ float sigmoidf_(float x) {
    return 1.0f / (1.0f + expf(-x));
}
static __device__ __forceinline__ float tanh_fast(float x) {
    float y; asm("tanh.approx.f32 %0, %1;" : "=f"(y) : "f"(x)); return y;
}
static __device__ __forceinline__ float rcp_fast(float x) {
    float y; asm("rcp.approx.f32 %0, %1;" : "=f"(y) : "f"(x)); return y;
}

__global__ void __launch_bounds__(96, 1)
k_all(const float* __restrict__ params,
      const float* __restrict__ covp,
      const float* __restrict__ init_states,
      const float* __restrict__ zin,
      float* __restrict__ out)
{
    extern __shared__ float smem[];
    float* sZ  = smem;                   // [384][33]
    float* sSv = smem + SZ_Z;            // [3][126][32]
    float* sD  = smem + SZ_Z + SZ_SV;    // [125][96]
    __shared__ bool sLast;

    const int tid  = threadIdx.x;
    const int ch   = tid >> 5;           // warp index = channel
    const int lane = tid & 31;
    const int b    = (blockIdx.x << 5) + lane;
    const int s    = ch * BB + b;        // column in g_F

    // ---------- stage this block's measurements into smem (coalesced) ----------
    {
        const float* zblk = zin + (size_t)(blockIdx.x << 5) * (TT * 3);
#pragma unroll 4
        for (int lb = 0; lb < 32; lb++) {
            const float4 vz = reinterpret_cast<const float4*>(zblk + lb * 384)[tid];
            const int k = tid << 2;
            sZ[(k + 0) * 33 + lb] = vz.x;
            sZ[(k + 1) * 33 + lb] = vz.y;
            sZ[(k + 2) * 33 + lb] = vz.z;
            sZ[(k + 3) * 33 + lb] = vz.w;
        }
    }

    const float DT     = 1.0f / 120.0f;
    const float TWO_PI = 6.28318530717958647692f;
    const float INV2PI = 0.15915494309189533577f;
    const float FOLD   = 4.71238898038468985769f;

    const float friction = (tanhf(params[0]) + 1.0f) * 0.01f;
    const float damping  = (tanhf(params[1]) + 1.0f) * 0.01f;

    const float r     = sigmoidf_(covp[ch]);
    const float qp    = sigmoidf_(covp[ch == 2 ? 5 : 3]);
    const float qv    = sigmoidf_(covp[ch == 2 ? 6 : 4]);
    const float gd    = 1.0f - DT * damping;
    const float Df    = DT * friction;
    const float Ag    = DT * friction * 100.0f;
    const float gdmAg = gd - Ag;
    const bool  ang   = (ch == 2);

    float p, v, Pa = 0.01f, Pb = 0.0f, Pc = 0.01f;
    {
        const int pi = ang ? 4 : ch;
        const int vi = ang ? 5 : (ch + 2);
        p = init_states[b * 6 + pi];
        v = init_states[b * 6 + vi];
    }

    __syncthreads();   // z staged

#define ZLDS(t) sZ[((t) * 3 + ch) * 33 + lane]

    // =========================== FORWARD EKF (store filtered only) ===========================
#define FW_STEP(tc, zc)                                                          \
    do {                                                                         \
        float g_, spv_;                                                          \
        if (!ang) {                                                              \
            const float th = tanh_fast(100.0f * v);                              \
            spv_ = __fmaf_rn(-Df, th, gd * v);                                   \
            g_   = __fmaf_rn(Ag, th * th, gdmAg);                                \
        } else { spv_ = v * gd; g_ = gd; }                                       \
        const float spp_ = __fmaf_rn(DT, v, p);                                  \
        const float bdc  = __fmaf_rn(DT, Pc, Pb);                                \
        const float ap   = __fmaf_rn(DT, Pb + bdc, Pa) + qp;                     \
        const float bp   = g_ * bdc;                                             \
        const float cpv  = __fmaf_rn(g_ * g_, Pc, qv);                           \
        float innov = (zc) - spp_;                                               \
        if (ang) innov = innov - TWO_PI * rintf(innov * INV2PI);                 \
        const float inv = rcp_fast(ap + r);                                      \
        const float K0  = ap * inv;                                              \
        const float K1  = bp * inv;                                              \
        p  = __fmaf_rn(K0, innov, spp_);                                         \
        v  = __fmaf_rn(K1, innov, spv_);                                         \
        Pa = r * K0;                                                             \
        Pb = r * K1;                                                             \
        Pc = __fmaf_rn(-K1, bp, cpv);                                            \
        if ((tc) >= 2 && (tc) <= 126) {                                          \
            const int m_ = (tc) - 2;                                             \
            g_F[m_ * SS + s] = make_float4(p, v, Pa, Pb);                        \
            sD[m_ * 96 + tid] = Pc;                                              \
        }                                                                        \
    } while (0)

    {
        float zcur = ZLDS(0);
#pragma unroll 4
        for (int t = 0; t < TT; t++) {
            const float znext = (t + 1 < TT) ? ZLDS(t + 1) : 0.0f;
            FW_STEP(t, zcur);
            zcur = znext;
        }
    }
#undef FW_STEP

    // loss at t = 127 (smoothed == filtered)
    float acc;
    {
        const float zf = ZLDS(TT - 1);
        float e = zf - p;
        if (ang) {
            e = (e >  FOLD) ? e - TWO_PI : e;
            e = (e < -FOLD) ? e + TWO_PI : e;
        }
        const float Sv = Pa + r;
        sSv[(ch * NSLOT + 125) * 32 + lane] = Sv;
        acc = Sv * e * e;
    }

    // =========================== BACKWARD RTS (recompute G from filtered) ===========================
    // carry = smoothed at t+1 (initially filtered at 127)
    float c0 = p, c1 = v, Q00 = Pa, Q01 = Pb, Q11 = Pc;

    float4 Fa[4], Fb[4];
    float  Ca[4], Cb[4], Za[4], Zb[4];
#pragma unroll
    for (int j = 0; j < 4; j++) {
        Fa[j] = make_float4(0,0,0,0); Fb[j] = Fa[j];
        Ca[j] = Cb[j] = Za[j] = Zb[j] = 0.0f;
    }

#define BW_LOAD(F_, C_, Z_, tq)                                                  \
    do { if ((tq) >= 2) {                                                        \
        const int _m = (tq) - 2;                                                 \
        F_ = g_F[_m * SS + s];                                                   \
        C_ = sD[_m * 96 + tid];                                                  \
        Z_ = ZLDS(tq);                                                           \
    } } while (0)

#define BW_STEP(Fv, Cv, Zv, tc)                                                  \
    do { if ((tc) >= 2) {                                                        \
        const float fp = (Fv).x, fv = (Fv).y, fa = (Fv).z, fb = (Fv).w;          \
        const float fc = (Cv);                                                   \
        float g_, spv_;                                                          \
        if (!ang) {                                                              \
            const float th = tanh_fast(100.0f * fv);                             \
            spv_ = __fmaf_rn(-Df, th, gd * fv);                                  \
            g_   = __fmaf_rn(Ag, th * th, gdmAg);                                \
        } else { spv_ = fv * gd; g_ = gd; }                                      \
        const float spp_ = __fmaf_rn(DT, fv, fp);                                \
        const float bdc  = __fmaf_rn(DT, fc, fb);                                \
        const float ap   = __fmaf_rn(DT, fb + bdc, fa) + qp;                     \
        const float bp   = g_ * bdc;                                             \
        const float cpv  = __fmaf_rn(g_ * g_, fc, qv);                           \
        const float idet = rcp_fast(__fmaf_rn(ap, cpv, -bp * bp));               \
        const float cpvI = cpv * idet;                                           \
        const float bpI  = bp  * idet;                                           \
        const float apI  = ap  * idet;                                           \
        const float u0 = __fmaf_rn(DT, fb, fa);                                  \
        const float u1 = g_ * fb;                                                \
        const float w0 = bdc;                                                    \
        const float w1 = g_ * fc;                                                \
        const float G00 = __fmaf_rn(u0, cpvI, -u1 * bpI);                        \
        const float G01 = __fmaf_rn(u1, apI,  -u0 * bpI);                        \
        const float G10 = __fmaf_rn(w0, cpvI, -w1 * bpI);                        \
        const float G11 = __fmaf_rn(w1, apI,  -w0 * bpI);                        \
        const float ds0 = c0 - spp_;                                             \
        const float ds1 = c1 - spv_;                                             \
        const float ssp = __fmaf_rn(G00, ds0, __fmaf_rn(G01, ds1, fp));          \
        const float ssv = __fmaf_rn(G10, ds0, __fmaf_rn(G11, ds1, fv));          \
        const float E00 = Q00 - ap;                                              \
        const float E01 = Q01 - bp;                                              \
        const float E11 = Q11 - cpv;                                             \
        const float M00 = __fmaf_rn(G00, E00, G01 * E01);                        \
        const float M01 = __fmaf_rn(G00, E01, G01 * E11);                        \
        const float M10 = __fmaf_rn(G10, E00, G11 * E01);                        \
        const float M11 = __fmaf_rn(G10, E01, G11 * E11);                        \
        const float nQ00 = __fmaf_rn(M00, G00, __fmaf_rn(M01, G01, fa));         \
        const float nQ01 = __fmaf_rn(M00, G10, __fmaf_rn(M01, G11, fb));         \
        const float nQ11 = __fmaf_rn(M10, G10, __fmaf_rn(M11, G11, fc));         \
        c0 = ssp; c1 = ssv; Q00 = nQ00; Q01 = nQ01; Q11 = nQ11;                  \
        const float Sv = nQ00 + r;                                               \
        float e = (Zv) - ssp;                                                    \
        if (ang) {                                                               \
            e = (e >  FOLD) ? e - TWO_PI : e;                                    \
            e = (e < -FOLD) ? e + TWO_PI : e;                                    \
        }                                                                        \
        acc = __fmaf_rn(Sv * e, e, acc);                                         \
        sSv[(ch * NSLOT + ((tc) - 2)) * 32 + lane] = Sv;                         \
    } } while (0)

#pragma unroll
    for (int j = 0; j < 4; j++) BW_LOAD(Fa[j], Ca[j], Za[j], 126 - j);
#pragma unroll
    for (int j = 0; j < 4; j++) BW_LOAD(Fb[j], Cb[j], Zb[j], 122 - j);

    for (int ii = 0; ii < 16; ii++) {
        const int head_a = 126 - 8 * ii;
        const int pre_a  = head_a - 8;
#pragma unroll
        for (int j = 0; j < 4; j++) {
            const float4 Fv = Fa[j];
            const float  Cv = Ca[j], Zv = Za[j];
            BW_LOAD(Fa[j], Ca[j], Za[j], pre_a - j);
            BW_STEP(Fv, Cv, Zv, head_a - j);
        }
        const int head_b = head_a - 4;
        const int pre_b  = head_b - 8;
#pragma unroll
        for (int j = 0; j < 4; j++) {
            const float4 Fv = Fb[j];
            const float  Cv = Cb[j], Zv = Zb[j];
            BW_LOAD(Fb[j], Cb[j], Zb[j], pre_b - j);
            BW_STEP(Fv, Cv, Zv, head_b - j);
        }
    }
#undef BW_LOAD
#undef BW_STEP
#undef ZLDS

    // =========================== in-block combine ===========================
    __syncthreads();

    float total = acc;
    // 126*32 = 4032 = 42 * 96 exactly
    for (int idx = tid; idx < NSLOT * 32; idx += 96) {
        const int u = idx >> 5;
        const int l = idx & 31;
        total += sSv[(0 * NSLOT + u) * 32 + l]
               * sSv[(1 * NSLOT + u) * 32 + l]
               * sSv[(2 * NSLOT + u) * 32 + l];
    }
    // warp-level reduce, then 3 partials via smem
#pragma unroll
    for (int k = 16; k > 0; k >>= 1)
        total += __shfl_xor_sync(0xffffffffu, total, k);
    __syncthreads();            // all Sv reads done; reuse smem front as scratch
    if (lane == 0) sSv[ch] = total;
    __syncthreads();
    if (tid == 0) g_bsum[blockIdx.x] = sSv[0] + sSv[1] + sSv[2];
    __threadfence();
    if (tid == 0) {
        const unsigned int old = atomicInc(&g_cnt, 127u);
        sLast = (old == 127u);
    }
    __syncthreads();

    // last block: deterministic final reduce of 128 partials
    if (sLast && tid < 32) {
        __threadfence();
        double ds = 0.0;
#pragma unroll
        for (int j = 0; j < 4; j++) ds += (double)g_bsum[tid * 4 + j];
#pragma unroll
        for (int k = 16; k > 0; k >>= 1)
            ds += __shfl_xor_sync(0xffffffffu, ds, k);
        if (tid == 0) out[0] = (float)ds;
    }
}

// ---------------- launch ----------------
extern "C" void kernel_launch(void* const* d_in, const int* in_sizes, int n_in,
                              void* d_out, int out_size) {
    const float* params = nullptr;
    const float* covp   = nullptr;
    const float* init   = nullptr;
    const float* meas   = nullptr;

    for (int i = 0; i < n_in; i++) {
        if      (in_sizes[i] == 4)            params = (const float*)d_in[i];
        else if (in_sizes[i] == 7)            covp   = (const float*)d_in[i];
        else if (in_sizes[i] == BB * 6)       init   = (const float*)d_in[i];
        else if (in_sizes[i] == BB * TT * 3)  meas   = (const float*)d_in[i];
    }
    if (!params && n_in > 0) params = (const float*)d_in[0];
    if (!covp   && n_in > 1) covp   = (const float*)d_in[1];
    if (!init   && n_in > 2) init   = (const float*)d_in[2];
    if (!meas   && n_in > 3) meas   = (const float*)d_in[3];

    static int smem_set = 0;
    if (!smem_set) {
        cudaFuncSetAttribute(k_all, cudaFuncAttributeMaxDynamicSharedMemorySize,
                             SMEM_BYTES);
        smem_set = 1;
    }

    k_all<<<128, 96, SMEM_BYTES>>>(params, covp, init, meas, (float*)d_out);
}

// round 13
// speedup vs baseline: 2.2286x; 1.1324x over previous
#include <cuda_runtime.h>
#include <math.h>

#define BB 4096
#define TT 128
#define SS 12288              // 3 * BB channel-chains
#define NSLOT 126             // loss slots u = t-2, t in [2,127]
#define NG 125                // filtered-history slots, t in [2,126], m = t-2

// shared memory layout (floats)
#define SZ_Z   (384 * 33)             // z staged: [k=t*3+ch][lane] padded
#define SZ_SV  (3 * NSLOT * 32)       // Sv table: [ch][u][lane]
#define SZ_D   (NG * 96)              // Pc history: [m][tid]
#define SMEM_FLOATS (SZ_Z + SZ_SV + SZ_D)
#define SMEM_BYTES  (SMEM_FLOATS * 4)

// ---------------- device scratch (no allocations allowed) ----------------
__device__ float4 g_F[NG * SS];    // filtered p,v,Pa,Pb
__device__ float  g_bsum[128];     // per-block partials
__device__ unsigned int g_cnt;     // last-block gate (self-resetting)

static __device__ __forceinline__ float sigmoidf_(float x) {
    return 1.0f / (1.0f + expf(-x));
}
static __device__ __forceinline__ float tanh_fast(float x) {
    float y; asm("tanh.approx.f32 %0, %1;" : "=f"(y) : "f"(x)); return y;
}
static __device__ __forceinline__ float rcp_fast(float x) {
    float y; asm("rcp.approx.f32 %0, %1;" : "=f"(y) : "f"(x)); return y;
}

__global__ void __launch_bounds__(96, 1)
k_all(const float* __restrict__ params,
      const float* __restrict__ covp,
      const float* __restrict__ init_states,
      const float* __restrict__ zin,
      float* __restrict__ out)
{
    extern __shared__ float smem[];
    float* sZ  = smem;                   // [384][33]
    float* sSv = smem + SZ_Z;            // [3][126][32]
    float* sD  = smem + SZ_Z + SZ_SV;    // [125][96]
    __shared__ bool sLast;

    const int tid  = threadIdx.x;
    const int ch   = tid >> 5;           // warp index = channel
    const int lane = tid & 31;
    const int b    = (blockIdx.x << 5) + lane;
    const int s    = ch * BB + b;        // column in g_F

    // ---------- stage this block's measurements into smem (coalesced) ----------
    {
        const float* zblk = zin + (size_t)(blockIdx.x << 5) * (TT * 3);
#pragma unroll 4
        for (int lb = 0; lb < 32; lb++) {
            const float4 vz = reinterpret_cast<const float4*>(zblk + lb * 384)[tid];
            const int k = tid << 2;
            sZ[(k + 0) * 33 + lb] = vz.x;
            sZ[(k + 1) * 33 + lb] = vz.y;
            sZ[(k + 2) * 33 + lb] = vz.z;
            sZ[(k + 3) * 33 + lb] = vz.w;
        }
    }

    const float DT     = 1.0f / 120.0f;
    const float TWO_PI = 6.28318530717958647692f;
    const float INV2PI = 0.15915494309189533577f;
    const float FOLD   = 4.71238898038468985769f;

    const float friction = (tanhf(params[0]) + 1.0f) * 0.01f;
    const float damping  = (tanhf(params[1]) + 1.0f) * 0.01f;

    const bool  ang   = (ch == 2);
    const float r     = sigmoidf_(covp[ch]);
    const float qp    = sigmoidf_(covp[ang ? 5 : 3]);
    const float qv    = sigmoidf_(covp[ang ? 6 : 4]);
    const float gd    = 1.0f - DT * damping;
    // channel-selected constants -> one uniform branch-free code path
    const float Df_c    = ang ? 0.0f : DT * friction;
    const float Ag_c    = ang ? 0.0f : DT * friction * 100.0f;
    const float gdmAg_c = gd - Ag_c;
    const float wTP     = ang ? TWO_PI : 0.0f;        // innovation wrap gain
    const float FOLD_c  = ang ? FOLD : 3.0e38f;       // fold sentinel

    float p, v, Pa = 0.01f, Pb = 0.0f, Pc = 0.01f;
    {
        const int pi = ang ? 4 : ch;
        const int vi = ang ? 5 : (ch + 2);
        p = init_states[b * 6 + pi];
        v = init_states[b * 6 + vi];
    }

    __syncthreads();   // z staged

#define ZLDS(t) sZ[((t) * 3 + ch) * 33 + lane]

    // =========================== FORWARD EKF (branch-free step) ===========================
#define FW_MATH(zc)                                                              \
    do {                                                                         \
        const float th   = tanh_fast(100.0f * v);                                \
        const float spv_ = __fmaf_rn(-Df_c, th, gd * v);                         \
        const float g_   = __fmaf_rn(Ag_c, th * th, gdmAg_c);                    \
        const float spp_ = __fmaf_rn(DT, v, p);                                  \
        const float bdc  = __fmaf_rn(DT, Pc, Pb);                                \
        const float ap   = __fmaf_rn(DT, Pb + bdc, Pa) + qp;                     \
        const float bp   = g_ * bdc;                                             \
        const float cpv  = __fmaf_rn(g_ * g_, Pc, qv);                           \
        float innov = (zc) - spp_;                                               \
        innov = __fmaf_rn(-wTP, rintf(innov * INV2PI), innov);                   \
        const float inv = rcp_fast(ap + r);                                      \
        const float K0  = ap * inv;                                              \
        const float K1  = bp * inv;                                              \
        p  = __fmaf_rn(K0, innov, spp_);                                         \
        v  = __fmaf_rn(K1, innov, spv_);                                         \
        Pa = r * K0;                                                             \
        Pb = r * K1;                                                             \
        Pc = __fmaf_rn(-K1, bp, cpv);                                            \
    } while (0)

    {
        float zcur = ZLDS(0);
        // t = 0, 1 peeled (no history store)
        {
            const float znext = ZLDS(1);
            FW_MATH(zcur);
            zcur = znext;
        }
        {
            const float znext = ZLDS(2);
            FW_MATH(zcur);
            zcur = znext;
        }
        // t in [2,126]: store always (no guard)
#pragma unroll 5
        for (int t = 2; t <= 126; t++) {
            const float znext = ZLDS(t + 1);
            FW_MATH(zcur);
            const int m_ = t - 2;
            g_F[m_ * SS + s] = make_float4(p, v, Pa, Pb);
            sD[m_ * 96 + tid] = Pc;
            zcur = znext;
        }
        // t = 127 peeled (no store)
        FW_MATH(zcur);
    }
#undef FW_MATH

    // loss at t = 127 (smoothed == filtered)
    float acc;
    {
        const float zf = ZLDS(TT - 1);
        float e = zf - p;
        e = (e >  FOLD_c) ? e - TWO_PI : e;
        e = (e < -FOLD_c) ? e + TWO_PI : e;
        const float Sv = Pa + r;
        sSv[(ch * NSLOT + 125) * 32 + lane] = Sv;
        acc = Sv * e * e;
    }

    // =========================== BACKWARD RTS (branch-free, clamped prefetch) ===========================
    float c0 = p, c1 = v, Q00 = Pa, Q01 = Pb, Q11 = Pc;

    float4 Fa[4], Fb[4];
    float  Ca[4], Cb[4], Za[4], Zb[4];

#define BW_LOADC(F_, C_, Z_, tq)                                                 \
    do {                                                                         \
        const int _m = max((tq) - 2, 0);                                         \
        F_ = g_F[_m * SS + s];                                                   \
        C_ = sD[_m * 96 + tid];                                                  \
        Z_ = sZ[((_m + 2) * 3 + ch) * 33 + lane];                                \
    } while (0)

#define BW_STEP(Fv, Cv, Zv, tc)                                                  \
    do {                                                                         \
        const float fp = (Fv).x, fv = (Fv).y, fa = (Fv).z, fb = (Fv).w;          \
        const float fc = (Cv);                                                   \
        const float th   = tanh_fast(100.0f * fv);                               \
        const float spv_ = __fmaf_rn(-Df_c, th, gd * fv);                        \
        const float g_   = __fmaf_rn(Ag_c, th * th, gdmAg_c);                    \
        const float spp_ = __fmaf_rn(DT, fv, fp);                                \
        const float bdc  = __fmaf_rn(DT, fc, fb);                                \
        const float ap   = __fmaf_rn(DT, fb + bdc, fa) + qp;                     \
        const float bp   = g_ * bdc;                                             \
        const float cpv  = __fmaf_rn(g_ * g_, fc, qv);                           \
        const float idet = rcp_fast(__fmaf_rn(ap, cpv, -bp * bp));               \
        const float cpvI = cpv * idet;                                           \
        const float bpI  = bp  * idet;                                           \
        const float apI  = ap  * idet;                                           \
        const float u0 = __fmaf_rn(DT, fb, fa);                                  \
        const float u1 = g_ * fb;                                                \
        const float w0 = bdc;                                                    \
        const float w1 = g_ * fc;                                                \
        const float G00 = __fmaf_rn(u0, cpvI, -u1 * bpI);                        \
        const float G01 = __fmaf_rn(u1, apI,  -u0 * bpI);                        \
        const float G10 = __fmaf_rn(w0, cpvI, -w1 * bpI);                        \
        const float G11 = __fmaf_rn(w1, apI,  -w0 * bpI);                        \
        const float ds0 = c0 - spp_;                                             \
        const float ds1 = c1 - spv_;                                             \
        const float ssp = __fmaf_rn(G00, ds0, __fmaf_rn(G01, ds1, fp));          \
        const float ssv = __fmaf_rn(G10, ds0, __fmaf_rn(G11, ds1, fv));          \
        const float E00 = Q00 - ap;                                              \
        const float E01 = Q01 - bp;                                              \
        const float E11 = Q11 - cpv;                                             \
        const float M00 = __fmaf_rn(G00, E00, G01 * E01);                        \
        const float M01 = __fmaf_rn(G00, E01, G01 * E11);                        \
        const float M10 = __fmaf_rn(G10, E00, G11 * E01);                        \
        const float M11 = __fmaf_rn(G10, E01, G11 * E11);                        \
        const float nQ00 = __fmaf_rn(M00, G00, __fmaf_rn(M01, G01, fa));         \
        const float nQ01 = __fmaf_rn(M00, G10, __fmaf_rn(M01, G11, fb));         \
        const float nQ11 = __fmaf_rn(M10, G10, __fmaf_rn(M11, G11, fc));         \
        c0 = ssp; c1 = ssv; Q00 = nQ00; Q01 = nQ01; Q11 = nQ11;                  \
        const float Sv = nQ00 + r;                                               \
        float e = (Zv) - ssp;                                                    \
        e = (e >  FOLD_c) ? e - TWO_PI : e;                                      \
        e = (e < -FOLD_c) ? e + TWO_PI : e;                                      \
        acc = __fmaf_rn(Sv * e, e, acc);                                         \
        sSv[(ch * NSLOT + ((tc) - 2)) * 32 + lane] = Sv;                         \
    } while (0)

    // preload: Fa[j] <- t=126-j, Fb[j] <- t=122-j
#pragma unroll
    for (int j = 0; j < 4; j++) BW_LOADC(Fa[j], Ca[j], Za[j], 126 - j);
#pragma unroll
    for (int j = 0; j < 4; j++) BW_LOADC(Fb[j], Cb[j], Zb[j], 122 - j);

    // main loop: 15 x 8 = 120 steps, t = 126 down to 7 (no guards)
    for (int ii = 0; ii < 15; ii++) {
        const int head_a = 126 - 8 * ii;
        const int pre_a  = head_a - 8;
#pragma unroll
        for (int j = 0; j < 4; j++) {
            const float4 Fv = Fa[j];
            const float  Cv = Ca[j], Zv = Za[j];
            BW_LOADC(Fa[j], Ca[j], Za[j], pre_a - j);
            BW_STEP(Fv, Cv, Zv, head_a - j);
        }
        const int head_b = head_a - 4;
        const int pre_b  = head_b - 8;
#pragma unroll
        for (int j = 0; j < 4; j++) {
            const float4 Fv = Fb[j];
            const float  Cv = Cb[j], Zv = Zb[j];
            BW_LOADC(Fb[j], Cb[j], Zb[j], pre_b - j);
            BW_STEP(Fv, Cv, Zv, head_b - j);
        }
    }
    // tail: t = 6,5,4,3 from bank A, t = 2 from bank B (no loads, no guards)
    BW_STEP(Fa[0], Ca[0], Za[0], 6);
    BW_STEP(Fa[1], Ca[1], Za[1], 5);
    BW_STEP(Fa[2], Ca[2], Za[2], 4);
    BW_STEP(Fa[3], Ca[3], Za[3], 3);
    BW_STEP(Fb[0], Cb[0], Zb[0], 2);
#undef BW_LOADC
#undef BW_STEP
#undef ZLDS

    // =========================== in-block combine ===========================
    __syncthreads();

    float total = acc;
    // 126*32 = 4032 = 42 * 96 exactly
    for (int idx = tid; idx < NSLOT * 32; idx += 96) {
        const int u = idx >> 5;
        const int l = idx & 31;
        total += sSv[(0 * NSLOT + u) * 32 + l]
               * sSv[(1 * NSLOT + u) * 32 + l]
               * sSv[(2 * NSLOT + u) * 32 + l];
    }
    // warp-level reduce, then 3 partials via smem
#pragma unroll
    for (int k = 16; k > 0; k >>= 1)
        total += __shfl_xor_sync(0xffffffffu, total, k);
    __syncthreads();            // all Sv reads done; reuse smem front as scratch
    if (lane == 0) sSv[ch] = total;
    __syncthreads();
    if (tid == 0) g_bsum[blockIdx.x] = sSv[0] + sSv[1] + sSv[2];
    __threadfence();
    if (tid == 0) {
        const unsigned int old = atomicInc(&g_cnt, 127u);
        sLast = (old == 127u);
    }
    __syncthreads();

    // last block: deterministic final reduce of 128 partials
    if (sLast && tid < 32) {
        __threadfence();
        double ds = 0.0;
#pragma unroll
        for (int j = 0; j < 4; j++) ds += (double)g_bsum[tid * 4 + j];
#pragma unroll
        for (int k = 16; k > 0; k >>= 1)
            ds += __shfl_xor_sync(0xffffffffu, ds, k);
        if (tid == 0) out[0] = (float)ds;
    }
}

// ---------------- launch ----------------
extern "C" void kernel_launch(void* const* d_in, const int* in_sizes, int n_in,
                              void* d_out, int out_size) {
    const float* params = nullptr;
    const float* covp   = nullptr;
    const float* init   = nullptr;
    const float* meas   = nullptr;

    for (int i = 0; i < n_in; i++) {
        if      (in_sizes[i] == 4)            params = (const float*)d_in[i];
        else if (in_sizes[i] == 7)            covp   = (const float*)d_in[i];
        else if (in_sizes[i] == BB * 6)       init   = (const float*)d_in[i];
        else if (in_sizes[i] == BB * TT * 3)  meas   = (const float*)d_in[i];
    }
    if (!params && n_in > 0) params = (const float*)d_in[0];
    if (!covp   && n_in > 1) covp   = (const float*)d_in[1];
    if (!init   && n_in > 2) init   = (const float*)d_in[2];
    if (!meas   && n_in > 3) meas   = (const float*)d_in[3];

    static int smem_set = 0;
    if (!smem_set) {
        cudaFuncSetAttribute(k_all, cudaFuncAttributeMaxDynamicSharedMemorySize,
                             SMEM_BYTES);
        smem_set = 1;
    }

    k_all<<<128, 96, SMEM_BYTES>>>(params, covp, init, meas, (float*)d_out);
}